// round 5
// baseline (speedup 1.0000x reference)
#include <cuda_runtime.h>
#include <cstdint>
#include <cstddef>

#define IN_CH  4096
#define OUT_CH 4096
#define BATCH  8192

#define M_TILE 128
#define N_TILE 256
#define KC     32                    // K floats per mainloop chunk
#define NCHUNK (IN_CH / KC)          // 128
#define STAGES 3

#define ROWP   36                    // padded row stride in floats (144 B, 16B-aligned)
#define A_FLOATS (M_TILE * ROWP)     // 4608 floats = 18432 B
#define B_FLOATS (N_TILE * ROWP)     // 9216 floats = 36864 B
#define STAGE_BYTES ((A_FLOATS + B_FLOATS) * 4)   // 55296 B
#define SMEM_TOTAL  (STAGES * STAGE_BYTES)        // 165888 B

// persistent scratch (static __device__ allocation is allowed)
__device__ float g_W[(size_t)OUT_CH * IN_CH];     // 64 MB dense tf32-rounded W
__device__ float g_X[(size_t)BATCH * IN_CH];      // 128 MB tf32-rounded x

// ---------------------------------------------------------------- helpers

static __device__ __forceinline__ uint32_t smem_u32(const void* p) {
    return (uint32_t)__cvta_generic_to_shared(p);
}
static __device__ __forceinline__ void cp_async16(uint32_t dst, const void* src) {
    asm volatile("cp.async.cg.shared.global [%0], [%1], 16;\n" :: "r"(dst), "l"(src) : "memory");
}
static __device__ __forceinline__ float tf32_rna(float v) {
    uint32_t o;
    asm("cvt.rna.tf32.f32 %0, %1;" : "=r"(o) : "f"(v));
    return __uint_as_float(o);
}
static __device__ __forceinline__ void mma_tf32(float* c, const uint32_t* a, const uint32_t* b) {
    asm volatile(
        "mma.sync.aligned.m16n8k8.row.col.f32.tf32.tf32.f32 "
        "{%0,%1,%2,%3}, {%4,%5,%6,%7}, {%8,%9}, {%0,%1,%2,%3};"
        : "+f"(c[0]), "+f"(c[1]), "+f"(c[2]), "+f"(c[3])
        : "r"(a[0]), "r"(a[1]), "r"(a[2]), "r"(a[3]), "r"(b[0]), "r"(b[1]));
}

// -------------------------------------------------------- prep kernels

__global__ void zero_w_kernel() {
    size_t i = (size_t)blockIdx.x * blockDim.x + threadIdx.x;
    if (i < ((size_t)OUT_CH * IN_CH) / 4) {
        reinterpret_cast<float4*>(g_W)[i] = make_float4(0.f, 0.f, 0.f, 0.f);
    }
}

__global__ void round_x_kernel(const float* __restrict__ x) {
    size_t i = (size_t)blockIdx.x * blockDim.x + threadIdx.x;
    if (i < ((size_t)BATCH * IN_CH) / 4) {
        float4 v = reinterpret_cast<const float4*>(x)[i];
        v.x = tf32_rna(v.x); v.y = tf32_rna(v.y);
        v.z = tf32_rna(v.z); v.w = tf32_rna(v.w);
        reinterpret_cast<float4*>(g_X)[i] = v;
    }
}

__global__ void scatter_kernel(const float* __restrict__ w, const int* __restrict__ rows,
                               const int* __restrict__ cols, int nnz) {
    int i = blockIdx.x * blockDim.x + threadIdx.x;
    if (i < nnz) g_W[(size_t)rows[i] * IN_CH + cols[i]] = tf32_rna(w[i]);
}

// -------------------------------------------------------- GEMM kernel
// out[m, n] = sum_k X[m,k] * W[n,k] + bias[n]
// CTA tile 128(M) x 256(N), 8 warps in 2(M) x 4(N) grid, warp tile 64x64.
// mma.sync.m16n8k8 tf32 (base PTX — tcgen05 is not available on this target).

__global__ void __launch_bounds__(256, 1)
gemm_kernel(const float* __restrict__ bias, float* __restrict__ out) {
    extern __shared__ char smem[];
    const uint32_t sb = smem_u32(smem);
    const int t = threadIdx.x;
    const int w = t >> 5, lid = t & 31;
    const int g = lid >> 2, tig = lid & 3;           // mma group / thread-in-group
    const int warp_m = w >> 2, warp_n = w & 3;

    const int m_tile = blockIdx.x >> 4;              // n-inner: W wave-resident in L2
    const int n_tile = blockIdx.x & 15;
    const int m_base = m_tile * M_TILE;
    const int n_base = n_tile * N_TILE;

    const float* xg = g_X + (size_t)m_base * IN_CH;
    const float* wg = g_W + (size_t)n_base * IN_CH;

    auto fill = [&](int s, int c) {
        const uint32_t abase = sb + s * STAGE_BYTES;
        const uint32_t bbase = abase + A_FLOATS * 4;
        const float* xa = xg + c * KC;
        const float* wb = wg + c * KC;
        #pragma unroll
        for (int it = 0; it < 12; ++it) {
            int j = t + it * 256;
            if (j < 1024) {                          // A: 128 rows x 8 16B-chunks
                int row = j >> 3, kc = j & 7;
                cp_async16(abase + (uint32_t)(row * ROWP * 4 + kc * 16),
                           xa + (size_t)row * IN_CH + kc * 4);
            } else {                                 // B: 256 rows x 8 16B-chunks
                int jj = j - 1024;
                int row = jj >> 3, kc = jj & 7;
                cp_async16(bbase + (uint32_t)(row * ROWP * 4 + kc * 16),
                           wb + (size_t)row * IN_CH + kc * 4);
            }
        }
        asm volatile("cp.async.commit_group;" ::: "memory");
    };

    float acc[4][8][4];                              // [mf][nf][frag] = 128 regs
    #pragma unroll
    for (int mf = 0; mf < 4; ++mf)
        #pragma unroll
        for (int nf = 0; nf < 8; ++nf)
            #pragma unroll
            for (int q = 0; q < 4; ++q) acc[mf][nf][q] = 0.f;

    // fragment row offsets (floats) in the padded smem tiles
    int aOff[4], bOff[8];
    #pragma unroll
    for (int mf = 0; mf < 4; ++mf) aOff[mf] = (warp_m * 64 + mf * 16 + g) * ROWP;
    #pragma unroll
    for (int nf = 0; nf < 8; ++nf) bOff[nf] = (warp_n * 64 + nf * 8 + g) * ROWP;

    fill(0, 0);
    fill(1, 1);

    for (int i = 0; i < NCHUNK; ++i) {
        const int s = i % STAGES;
        if (i + 2 < NCHUNK) fill((i + 2) % STAGES, i + 2);

        if (i < NCHUNK - 2) {
            asm volatile("cp.async.wait_group 2;" ::: "memory");
        } else {
            asm volatile("cp.async.wait_group 0;" ::: "memory");
        }
        __syncthreads();                             // chunk i visible to all threads

        const float* sA = (const float*)(smem + s * STAGE_BYTES);
        const float* sB = sA + A_FLOATS;

        #pragma unroll
        for (int ks = 0; ks < 4; ++ks) {
            const int kk = ks * 8 + tig;
            uint32_t a[4][4], b[8][2];
            #pragma unroll
            for (int mf = 0; mf < 4; ++mf) {
                a[mf][0] = __float_as_uint(sA[aOff[mf] + kk]);
                a[mf][1] = __float_as_uint(sA[aOff[mf] + 8 * ROWP + kk]);
                a[mf][2] = __float_as_uint(sA[aOff[mf] + kk + 4]);
                a[mf][3] = __float_as_uint(sA[aOff[mf] + 8 * ROWP + kk + 4]);
            }
            #pragma unroll
            for (int nf = 0; nf < 8; ++nf) {
                b[nf][0] = __float_as_uint(sB[bOff[nf] + kk]);
                b[nf][1] = __float_as_uint(sB[bOff[nf] + kk + 4]);
            }
            #pragma unroll
            for (int mf = 0; mf < 4; ++mf)
                #pragma unroll
                for (int nf = 0; nf < 8; ++nf)
                    mma_tf32(acc[mf][nf], a[mf], b[nf]);
        }
        __syncthreads();                             // stage s free for refill
    }

    // epilogue: direct float2 stores, bias added in fp32
    #pragma unroll
    for (int nf = 0; nf < 8; ++nf) {
        const int col = n_base + warp_n * 64 + nf * 8 + tig * 2;
        const float bv0 = bias[col], bv1 = bias[col + 1];
        #pragma unroll
        for (int mf = 0; mf < 4; ++mf) {
            const int row = m_base + warp_m * 64 + mf * 16 + g;
            float2 v0 = make_float2(acc[mf][nf][0] + bv0, acc[mf][nf][1] + bv1);
            float2 v1 = make_float2(acc[mf][nf][2] + bv0, acc[mf][nf][3] + bv1);
            *reinterpret_cast<float2*>(&out[(size_t)row * OUT_CH + col]) = v0;
            *reinterpret_cast<float2*>(&out[(size_t)(row + 8) * OUT_CH + col]) = v1;
        }
    }
}

// -------------------------------------------------------- launch

extern "C" void kernel_launch(void* const* d_in, const int* in_sizes, int n_in,
                              void* d_out, int out_size) {
    const float* x    = (const float*)d_in[0];
    const float* sw   = (const float*)d_in[1];
    const float* bias = (const float*)d_in[2];
    const int*   rows = (const int*)d_in[3];
    const int*   cols = (const int*)d_in[4];
    const int    nnz  = in_sizes[1];
    float*       out  = (float*)d_out;

    cudaFuncSetAttribute(gemm_kernel, cudaFuncAttributeMaxDynamicSharedMemorySize, SMEM_TOTAL);

    const int zb = (int)((((size_t)OUT_CH * IN_CH) / 4 + 255) / 256);
    const int xb = (int)((((size_t)BATCH * IN_CH) / 4 + 255) / 256);
    zero_w_kernel<<<zb, 256>>>();
    round_x_kernel<<<xb, 256>>>(x);
    scatter_kernel<<<(nnz + 255) / 256, 256>>>(sw, rows, cols, nnz);
    gemm_kernel<<<(BATCH / M_TILE) * (OUT_CH / N_TILE), 256, SMEM_TOTAL>>>(bias, out);
}

// round 6
// speedup vs baseline: 1.9246x; 1.9246x over previous
#include <cuda_runtime.h>
#include <cuda_fp16.h>
#include <cstdint>
#include <cstddef>

#define IN_CH  4096
#define OUT_CH 4096
#define BATCH  8192

#define M_TILE 128
#define N_TILE 256
#define KC     64                    // K halves per mainloop chunk (128 B/row)
#define NCHUNK (IN_CH / KC)          // 64
#define STAGES 3

#define ROWP   36                    // padded row stride in b32 words (144 B)
#define A_WORDS (M_TILE * ROWP)      // 4608 words = 18432 B
#define B_WORDS (N_TILE * ROWP)      // 9216 words = 36864 B
#define STAGE_BYTES ((A_WORDS + B_WORDS) * 4)     // 55296 B
#define SMEM_TOTAL  (STAGES * STAGE_BYTES)        // 165888 B

// persistent scratch (static __device__ allocation is allowed)
__device__ __half g_Wh[(size_t)OUT_CH * IN_CH];   // 32 MB dense fp16 W
__device__ __half g_Xh[(size_t)BATCH * IN_CH];    // 64 MB fp16 x

// ---------------------------------------------------------------- helpers

static __device__ __forceinline__ uint32_t smem_u32(const void* p) {
    return (uint32_t)__cvta_generic_to_shared(p);
}
static __device__ __forceinline__ void cp_async16(uint32_t dst, const void* src) {
    asm volatile("cp.async.cg.shared.global [%0], [%1], 16;\n" :: "r"(dst), "l"(src) : "memory");
}
static __device__ __forceinline__ void mma_f16(float* c, const uint32_t* a, const uint32_t* b) {
    asm volatile(
        "mma.sync.aligned.m16n8k16.row.col.f32.f16.f16.f32 "
        "{%0,%1,%2,%3}, {%4,%5,%6,%7}, {%8,%9}, {%0,%1,%2,%3};"
        : "+f"(c[0]), "+f"(c[1]), "+f"(c[2]), "+f"(c[3])
        : "r"(a[0]), "r"(a[1]), "r"(a[2]), "r"(a[3]), "r"(b[0]), "r"(b[1]));
}

// -------------------------------------------------------- prep kernels

__global__ void zero_w_kernel() {
    size_t i = (size_t)blockIdx.x * blockDim.x + threadIdx.x;
    if (i < ((size_t)OUT_CH * IN_CH) / 8) {
        reinterpret_cast<uint4*>(g_Wh)[i] = make_uint4(0u, 0u, 0u, 0u);
    }
}

__global__ void round_x_kernel(const float* __restrict__ x) {
    size_t i = (size_t)blockIdx.x * blockDim.x + threadIdx.x;
    if (i < ((size_t)BATCH * IN_CH) / 4) {
        float4 v = reinterpret_cast<const float4*>(x)[i];
        __half2 h0 = make_half2(__float2half_rn(v.x), __float2half_rn(v.y));
        __half2 h1 = make_half2(__float2half_rn(v.z), __float2half_rn(v.w));
        reinterpret_cast<__half2*>(g_Xh)[i * 2 + 0] = h0;
        reinterpret_cast<__half2*>(g_Xh)[i * 2 + 1] = h1;
    }
}

__global__ void scatter_kernel(const float* __restrict__ w, const int* __restrict__ rows,
                               const int* __restrict__ cols, int nnz) {
    int i = blockIdx.x * blockDim.x + threadIdx.x;
    if (i < nnz) g_Wh[(size_t)rows[i] * IN_CH + cols[i]] = __float2half_rn(w[i]);
}

// -------------------------------------------------------- GEMM kernel
// out[m, n] = sum_k X[m,k] * W[n,k] + bias[n]
// CTA tile 128(M) x 256(N), 8 warps in 2(M) x 4(N) grid, warp tile 64x64.
// mma.sync.m16n8k16 fp16 (fp32 accumulate); same word-indexing scheme as the
// verified tf32 kernel — b32 words are now half-pairs, K=16 per MMA.

__global__ void __launch_bounds__(256, 1)
gemm_kernel(const float* __restrict__ bias, float* __restrict__ out) {
    extern __shared__ char smem[];
    const uint32_t sb = smem_u32(smem);
    const int t = threadIdx.x;
    const int w = t >> 5, lid = t & 31;
    const int g = lid >> 2, tig = lid & 3;           // mma group / thread-in-group
    const int warp_m = w >> 2, warp_n = w & 3;

    const int m_tile = blockIdx.x >> 4;              // n-inner: W wave-resident in L2
    const int n_tile = blockIdx.x & 15;
    const int m_base = m_tile * M_TILE;
    const int n_base = n_tile * N_TILE;

    const __half* xg = g_Xh + (size_t)m_base * IN_CH;
    const __half* wg = g_Wh + (size_t)n_base * IN_CH;

    auto fill = [&](int s, int c) {
        const uint32_t abase = sb + s * STAGE_BYTES;
        const uint32_t bbase = abase + A_WORDS * 4;
        const __half* xa = xg + c * KC;
        const __half* wb = wg + c * KC;
        #pragma unroll
        for (int it = 0; it < 12; ++it) {
            int j = t + it * 256;
            if (j < 1024) {                          // A: 128 rows x 8 16B-chunks
                int row = j >> 3, kc = j & 7;
                cp_async16(abase + (uint32_t)(row * ROWP * 4 + kc * 16),
                           xa + (size_t)row * IN_CH + kc * 8);
            } else {                                 // B: 256 rows x 8 16B-chunks
                int jj = j - 1024;
                int row = jj >> 3, kc = jj & 7;
                cp_async16(bbase + (uint32_t)(row * ROWP * 4 + kc * 16),
                           wb + (size_t)row * IN_CH + kc * 8);
            }
        }
        asm volatile("cp.async.commit_group;" ::: "memory");
    };

    float acc[4][8][4];                              // [mf][nf][frag] = 128 regs
    #pragma unroll
    for (int mf = 0; mf < 4; ++mf)
        #pragma unroll
        for (int nf = 0; nf < 8; ++nf)
            #pragma unroll
            for (int q = 0; q < 4; ++q) acc[mf][nf][q] = 0.f;

    // fragment row offsets (b32 words) in the padded smem tiles
    int aOff[4], bOff[8];
    #pragma unroll
    for (int mf = 0; mf < 4; ++mf) aOff[mf] = (warp_m * 64 + mf * 16 + g) * ROWP;
    #pragma unroll
    for (int nf = 0; nf < 8; ++nf) bOff[nf] = (warp_n * 64 + nf * 8 + g) * ROWP;

    fill(0, 0);
    fill(1, 1);

    for (int i = 0; i < NCHUNK; ++i) {
        const int s = i % STAGES;
        if (i + 2 < NCHUNK) fill((i + 2) % STAGES, i + 2);

        if (i < NCHUNK - 2) {
            asm volatile("cp.async.wait_group 2;" ::: "memory");
        } else {
            asm volatile("cp.async.wait_group 0;" ::: "memory");
        }
        __syncthreads();                             // chunk i visible to all threads

        const uint32_t* sA = (const uint32_t*)(smem + s * STAGE_BYTES);
        const uint32_t* sB = sA + A_WORDS;

        #pragma unroll
        for (int ks = 0; ks < 4; ++ks) {             // 4 x k16 per 64-half chunk
            const int kk = ks * 8 + tig;             // b32 word index in row
            uint32_t a[4][4], b[8][2];
            #pragma unroll
            for (int mf = 0; mf < 4; ++mf) {
                a[mf][0] = sA[aOff[mf] + kk];
                a[mf][1] = sA[aOff[mf] + 8 * ROWP + kk];
                a[mf][2] = sA[aOff[mf] + kk + 4];
                a[mf][3] = sA[aOff[mf] + 8 * ROWP + kk + 4];
            }
            #pragma unroll
            for (int nf = 0; nf < 8; ++nf) {
                b[nf][0] = sB[bOff[nf] + kk];
                b[nf][1] = sB[bOff[nf] + kk + 4];
            }
            #pragma unroll
            for (int mf = 0; mf < 4; ++mf)
                #pragma unroll
                for (int nf = 0; nf < 8; ++nf)
                    mma_f16(acc[mf][nf], a[mf], b[nf]);
        }
        __syncthreads();                             // stage s free for refill
    }

    // epilogue: direct float2 stores, bias added in fp32
    #pragma unroll
    for (int nf = 0; nf < 8; ++nf) {
        const int col = n_base + warp_n * 64 + nf * 8 + tig * 2;
        const float bv0 = bias[col], bv1 = bias[col + 1];
        #pragma unroll
        for (int mf = 0; mf < 4; ++mf) {
            const int row = m_base + warp_m * 64 + mf * 16 + g;
            float2 v0 = make_float2(acc[mf][nf][0] + bv0, acc[mf][nf][1] + bv1);
            float2 v1 = make_float2(acc[mf][nf][2] + bv0, acc[mf][nf][3] + bv1);
            *reinterpret_cast<float2*>(&out[(size_t)row * OUT_CH + col]) = v0;
            *reinterpret_cast<float2*>(&out[(size_t)(row + 8) * OUT_CH + col]) = v1;
        }
    }
}

// -------------------------------------------------------- launch

extern "C" void kernel_launch(void* const* d_in, const int* in_sizes, int n_in,
                              void* d_out, int out_size) {
    const float* x    = (const float*)d_in[0];
    const float* sw   = (const float*)d_in[1];
    const float* bias = (const float*)d_in[2];
    const int*   rows = (const int*)d_in[3];
    const int*   cols = (const int*)d_in[4];
    const int    nnz  = in_sizes[1];
    float*       out  = (float*)d_out;

    cudaFuncSetAttribute(gemm_kernel, cudaFuncAttributeMaxDynamicSharedMemorySize, SMEM_TOTAL);

    const int zb = (int)((((size_t)OUT_CH * IN_CH) / 8 + 255) / 256);
    const int xb = (int)((((size_t)BATCH * IN_CH) / 4 + 255) / 256);
    zero_w_kernel<<<zb, 256>>>();
    round_x_kernel<<<xb, 256>>>(x);
    scatter_kernel<<<(nnz + 255) / 256, 256>>>(sw, rows, cols, nnz);
    gemm_kernel<<<(BATCH / M_TILE) * (OUT_CH / N_TILE), 256, SMEM_TOTAL>>>(bias, out);
}